// round 8
// baseline (speedup 1.0000x reference)
#include <cuda_runtime.h>
#include <cuda_bf16.h>

#define NP      20
#define D       64
#define NROWS   16384
#define EPS2    1e-24f          // (1e-12)^2 under rsqrt

#define WPB     8
#define THREADS (WPB * 32)
#define NBLOCKS (NROWS / WPB)   // 2048

// packed f32x2 fma: acc = a*b + acc
__device__ __forceinline__ void fma2(unsigned long long& acc,
                                     unsigned long long a,
                                     unsigned long long b) {
    asm("fma.rn.f32x2 %0, %1, %2, %0;" : "+l"(acc) : "l"(a), "l"(b));
}

__global__ __launch_bounds__(THREADS, 2)
void user_memory_fused(const int* __restrict__ uidx,
                       const float* __restrict__ x,
                       const float* __restrict__ proto,
                       const float* __restrict__ W,
                       const float* __restrict__ b,
                       float* __restrict__ out)
{
    __shared__ float2 Wp[D / 2][D];     // Wp[kk][d] = {W[d][2kk], W[d][2kk+1]}
    __shared__ float  xs[WPB][D];

    const int tid  = threadIdx.x;
    const int warp = tid >> 5;
    const int lane = tid & 31;
    const int q    = lane & 15;         // float4 slot within a proto
    const int half = lane >> 4;         // which proto of each pair

    const int row = blockIdx.x * WPB + warp;

    // ---- 1) issue the entire anchor gather FIRST (10 independent LDG.128) ----
    const int u = __ldg(&uidx[row]);
    const float4* base =
        (const float4*)(proto + (size_t)u * (NP * D)) + half * (D / 4) + q;

    float4 a0 = __ldg(base + 0 * 32);
    float4 a1 = __ldg(base + 1 * 32);
    float4 a2 = __ldg(base + 2 * 32);
    float4 a3 = __ldg(base + 3 * 32);
    float4 a4 = __ldg(base + 4 * 32);
    float4 a5 = __ldg(base + 5 * 32);
    float4 a6 = __ldg(base + 6 * 32);
    float4 a7 = __ldg(base + 7 * 32);
    float4 a8 = __ldg(base + 8 * 32);
    float4 a9 = __ldg(base + 9 * 32);

    // ---- 2) stage W (packed k-pairs) + this warp's x row; runs under DRAM shadow ----
    #pragma unroll
    for (int i = tid; i < D * D / 2; i += THREADS) {
        int d = i >> 5, kk = i & 31;
        Wp[kk][d] = ((const float2*)W)[i];
    }
    {
        float2 v = ((const float2*)(x + (size_t)row * D))[lane];
        ((float2*)&xs[warp][0])[lane] = v;
    }
    __syncthreads();

    // ---- 3) matvec: lane owns dims (2*lane, 2*lane+1) ----
    unsigned long long h0 = 0ull, h1 = 0ull;   // packed even-k / odd-k partials
    #pragma unroll 8
    for (int kk = 0; kk < D / 2; ++kk) {
        ulonglong2 wv = *(const ulonglong2*)&Wp[kk][2 * lane];      // conflict-free
        unsigned long long xp = *(const unsigned long long*)&xs[warp][2 * kk]; // bcast
        fma2(h0, xp, wv.x);
        fma2(h1, xp, wv.y);
    }

    const float2 bb = ((const float2*)b)[lane];
    float2 p0 = *(float2*)&h0;
    float2 p1 = *(float2*)&h1;
    float hx = p0.x + p0.y + bb.x;
    float hy = p1.x + p1.y + bb.y;

    // normalize h -> z
    float nn = hx * hx + hy * hy;
    #pragma unroll
    for (int m = 16; m >= 1; m >>= 1)
        nn += __shfl_xor_sync(0xFFFFFFFFu, nn, m);
    float inv = rsqrtf(fmaxf(nn, EPS2));
    float zx = hx * inv, zy = hy * inv;

    // permute z into float4 anchor layout: zq = z[dims 4q..4q+3]
    float4 zq;
    zq.x = __shfl_sync(0xFFFFFFFFu, zx, 2 * q);
    zq.y = __shfl_sync(0xFFFFFFFFu, zy, 2 * q);
    zq.z = __shfl_sync(0xFFFFFFFFu, zx, 2 * q + 1);
    zq.w = __shfl_sync(0xFFFFFFFFu, zy, 2 * q + 1);

    // ---- 4) consume anchors: s = sum_p normalize(a_p) (2 protos/warp-instr) ----
    float4 s = make_float4(0.f, 0.f, 0.f, 0.f);

    #define PROC(A)                                                           \
    {                                                                         \
        float t = A.x * A.x + A.y * A.y + A.z * A.z + A.w * A.w;              \
        _Pragma("unroll")                                                     \
        for (int m = 8; m >= 1; m >>= 1)                                      \
            t += __shfl_xor_sync(0xFFFFFFFFu, t, m);                          \
        float iv = rsqrtf(fmaxf(t, EPS2));                                    \
        s.x = fmaf(A.x, iv, s.x);                                             \
        s.y = fmaf(A.y, iv, s.y);                                             \
        s.z = fmaf(A.z, iv, s.z);                                             \
        s.w = fmaf(A.w, iv, s.w);                                             \
    }

    PROC(a0); PROC(a1); PROC(a2); PROC(a3); PROC(a4);
    PROC(a5); PROC(a6); PROC(a7); PROC(a8); PROC(a9);
    #undef PROC

    // ---- 5) score = z . (s_half0 + s_half1); 32-lane reduce sums both halves ----
    float d = zq.x * s.x + zq.y * s.y + zq.z * s.z + zq.w * s.w;
    #pragma unroll
    for (int m = 16; m >= 1; m >>= 1)
        d += __shfl_xor_sync(0xFFFFFFFFu, d, m);

    if (lane == 0)
        out[row] = d;
}

extern "C" void kernel_launch(void* const* d_in, const int* in_sizes, int n_in,
                              void* d_out, int out_size) {
    const int*   uidx  = (const int*)d_in[0];
    const float* x     = (const float*)d_in[1];
    const float* proto = (const float*)d_in[2];
    const float* W     = (const float*)d_in[3];
    const float* b     = (const float*)d_in[4];
    float* out = (float*)d_out;

    user_memory_fused<<<NBLOCKS, THREADS>>>(uidx, x, proto, W, b, out);
}

// round 10
// speedup vs baseline: 1.1160x; 1.1160x over previous
#include <cuda_runtime.h>
#include <cuda_bf16.h>
#include <cstdint>

#define NP       20
#define D        64
#define NROWS    16384
#define EPS2     1e-24f              // (1e-12)^2 under rsqrt
#define ROWBYTES (NP * D * 4)        // 5120 B of anchors per row

#define WPB      4                   // warps per block
#define R        4                   // rows per warp
#define THREADS  (WPB * 32)          // 128
#define ROWSB    (WPB * R)           // 16
#define NBLOCKS  (NROWS / ROWSB)     // 1024

// dynamic smem layout
struct Smem {
    char   anc[ROWSB][ROWBYTES];     // 80 KB anchor staging
    float2 Wp[D / 2][D];             // Wp[kk][d] = {W[d][2kk], W[d][2kk+1]}  16 KB
    float  xs[ROWSB][D];             // 4 KB
};

__device__ __forceinline__ void fma2(unsigned long long& acc,
                                     unsigned long long a,
                                     unsigned long long b) {
    asm("fma.rn.f32x2 %0, %1, %2, %0;" : "+l"(acc) : "l"(a), "l"(b));
}

__device__ __forceinline__ void cp16(unsigned int dst, const void* src) {
    asm volatile("cp.async.cg.shared.global [%0], [%1], 16;"
                 :: "r"(dst), "l"(src));
}

__global__ __launch_bounds__(THREADS)
void user_memory_fused(const int* __restrict__ uidx,
                       const float* __restrict__ x,
                       const float* __restrict__ proto,
                       const float* __restrict__ W,
                       const float* __restrict__ b,
                       float* __restrict__ out)
{
    extern __shared__ char smem_raw[];
    Smem* sm = (Smem*)smem_raw;

    const int tid  = threadIdx.x;
    const int warp = tid >> 5;
    const int lane = tid & 31;
    const int q    = lane & 15;       // float4 slot within a proto
    const int half = lane >> 4;       // which proto of each pair

    const int rowbase = blockIdx.x * ROWSB + warp * R;
    const int rl      = warp * R;

    // ---- 1) issue the full anchor gather via cp.async (no register cost) ----
    #pragma unroll
    for (int r = 0; r < R; ++r) {
        const int u = __ldg(&uidx[rowbase + r]);
        const char* src = (const char*)proto + (size_t)u * ROWBYTES + lane * 16;
        unsigned int dst =
            (unsigned int)__cvta_generic_to_shared(&sm->anc[rl + r][0]) + lane * 16;
        #pragma unroll
        for (int c = 0; c < NP / 2; ++c)              // 512 B per cp per warp
            cp16(dst + c * 512, src + c * 512);
    }
    asm volatile("cp.async.commit_group;");

    // ---- 2) stage W (packed k-pairs) + x rows; streams under gather shadow ----
    #pragma unroll
    for (int i = tid; i < D * D / 2; i += THREADS) {
        int d = i >> 5, kk = i & 31;
        sm->Wp[kk][d] = ((const float2*)W)[i];
    }
    #pragma unroll
    for (int r = 0; r < R; ++r) {
        float2 v = ((const float2*)(x + (size_t)(rowbase + r) * D))[lane];
        ((float2*)&sm->xs[rl + r][0])[lane] = v;
    }
    __syncthreads();

    // ---- 3) matvec: lane owns dims (2*lane, 2*lane+1), R rows share W reads ----
    unsigned long long h0[R], h1[R];
    #pragma unroll
    for (int r = 0; r < R; ++r) { h0[r] = 0ull; h1[r] = 0ull; }

    #pragma unroll 4
    for (int kk = 0; kk < D / 2; ++kk) {
        ulonglong2 wv = *(const ulonglong2*)&sm->Wp[kk][2 * lane];
        #pragma unroll
        for (int r = 0; r < R; ++r) {
            unsigned long long xp =
                *(const unsigned long long*)&sm->xs[rl + r][2 * kk];  // bcast
            fma2(h0[r], xp, wv.x);
            fma2(h1[r], xp, wv.y);
        }
    }

    const float2 bb = ((const float2*)b)[lane];
    float zx[R], zy[R];
    {
        float hx[R], hy[R], nn[R];
        #pragma unroll
        for (int r = 0; r < R; ++r) {
            float2 p0 = *(float2*)&h0[r];
            float2 p1 = *(float2*)&h1[r];
            hx[r] = p0.x + p0.y + bb.x;
            hy[r] = p1.x + p1.y + bb.y;
            nn[r] = hx[r] * hx[r] + hy[r] * hy[r];
        }
        #pragma unroll
        for (int m = 16; m >= 1; m >>= 1) {
            #pragma unroll
            for (int r = 0; r < R; ++r)
                nn[r] += __shfl_xor_sync(0xFFFFFFFFu, nn[r], m);
        }
        #pragma unroll
        for (int r = 0; r < R; ++r) {
            float inv = rsqrtf(fmaxf(nn[r], EPS2));
            zx[r] = hx[r] * inv;
            zy[r] = hy[r] * inv;
        }
    }

    // permute z into float4 anchor layout: zq[r] = z[dims 4q..4q+3]
    float4 zq[R];
    #pragma unroll
    for (int r = 0; r < R; ++r) {
        zq[r].x = __shfl_sync(0xFFFFFFFFu, zx[r], 2 * q);
        zq[r].y = __shfl_sync(0xFFFFFFFFu, zy[r], 2 * q);
        zq[r].z = __shfl_sync(0xFFFFFFFFu, zx[r], 2 * q + 1);
        zq[r].w = __shfl_sync(0xFFFFFFFFu, zy[r], 2 * q + 1);
    }

    // ---- 4) wait for this warp's anchors; consume from smem ----
    asm volatile("cp.async.wait_group 0;" ::: "memory");
    __syncwarp();

    float4 s[R];
    #pragma unroll
    for (int r = 0; r < R; ++r) s[r] = make_float4(0.f, 0.f, 0.f, 0.f);

    #pragma unroll
    for (int c = 0; c < NP / 2; ++c) {
        float4 a[R];
        float  nn[R];
        #pragma unroll
        for (int r = 0; r < R; ++r)
            a[r] = *(const float4*)&sm->anc[rl + r][c * 512 + half * 256 + q * 16];
        #pragma unroll
        for (int r = 0; r < R; ++r)
            nn[r] = a[r].x * a[r].x + a[r].y * a[r].y
                  + a[r].z * a[r].z + a[r].w * a[r].w;
        #pragma unroll
        for (int m = 8; m >= 1; m >>= 1) {            // 16-lane reduce per half
            #pragma unroll
            for (int r = 0; r < R; ++r)
                nn[r] += __shfl_xor_sync(0xFFFFFFFFu, nn[r], m);
        }
        #pragma unroll
        for (int r = 0; r < R; ++r) {
            float iv = rsqrtf(fmaxf(nn[r], EPS2));
            s[r].x = fmaf(a[r].x, iv, s[r].x);
            s[r].y = fmaf(a[r].y, iv, s[r].y);
            s[r].z = fmaf(a[r].z, iv, s[r].z);
            s[r].w = fmaf(a[r].w, iv, s[r].w);
        }
    }

    // ---- 5) score = z . s ; full 32-lane reduce sums both proto halves ----
    #pragma unroll
    for (int r = 0; r < R; ++r) {
        float d = zq[r].x * s[r].x + zq[r].y * s[r].y
                + zq[r].z * s[r].z + zq[r].w * s[r].w;
        #pragma unroll
        for (int m = 16; m >= 1; m >>= 1)
            d += __shfl_xor_sync(0xFFFFFFFFu, d, m);
        if (lane == 0)
            out[rowbase + r] = d;
    }
}

extern "C" void kernel_launch(void* const* d_in, const int* in_sizes, int n_in,
                              void* d_out, int out_size) {
    const int*   uidx  = (const int*)d_in[0];
    const float* x     = (const float*)d_in[1];
    const float* proto = (const float*)d_in[2];
    const float* W     = (const float*)d_in[3];
    const float* b     = (const float*)d_in[4];
    float* out = (float*)d_out;

    const int smem_bytes = (int)sizeof(Smem);       // ~100 KB
    cudaFuncSetAttribute(user_memory_fused,
                         cudaFuncAttributeMaxDynamicSharedMemorySize, smem_bytes);
    user_memory_fused<<<NBLOCKS, THREADS, smem_bytes>>>(uidx, x, proto, W, b, out);
}

// round 11
// speedup vs baseline: 1.5863x; 1.4214x over previous
#include <cuda_runtime.h>
#include <cuda_bf16.h>
#include <cstdint>

#define NP      20
#define D       64
#define NROWS   16384
#define EPS2    1e-24f              // (1e-12)^2 under rsqrt

#define THREADS    256
#define MV_BLOCKS  256              // matvec: 64 rows/block
#define MV_R       8                // rows per warp in matvec
#define GA_WPB     8                // gather: 1 row/warp
#define GA_BLOCKS  (NROWS / GA_WPB) // 2048
#define NBLOCKS    (MV_BLOCKS + GA_BLOCKS)

__device__ float g_z[NROWS * D];    // normalized queries
__device__ int   g_flag[MV_BLOCKS]; // publish flags (zero-init at module load)

__device__ __forceinline__ void fma2(unsigned long long& acc,
                                     unsigned long long a,
                                     unsigned long long b) {
    asm("fma.rn.f32x2 %0, %1, %2, %0;" : "+l"(acc) : "l"(a), "l"(b));
}

__global__ __launch_bounds__(THREADS, 2)
void user_memory_overlap(const int* __restrict__ uidx,
                         const float* __restrict__ x,
                         const float* __restrict__ proto,
                         const float* __restrict__ W,
                         const float* __restrict__ b,
                         float* __restrict__ out)
{
    __shared__ float2 Wp[D / 2][D];          // 16 KB (matvec blocks only)
    __shared__ float  xs[MV_BLOCKS ? 64 : 1][D]; // 16 KB x staging

    const int tid  = threadIdx.x;
    const int warp = tid >> 5;
    const int lane = tid & 31;

    if (blockIdx.x < MV_BLOCKS) {
        // ================= MATVEC ROLE: z = normalize(x@W^T + b) =============
        const int rowbase = blockIdx.x * 64 + warp * MV_R;
        const int rl      = warp * MV_R;

        #pragma unroll
        for (int i = tid; i < D * D / 2; i += THREADS) {
            int d = i >> 5, kk = i & 31;
            Wp[kk][d] = ((const float2*)W)[i];
        }
        #pragma unroll
        for (int r = 0; r < MV_R; ++r) {
            float2 v = ((const float2*)(x + (size_t)(rowbase + r) * D))[lane];
            ((float2*)&xs[rl + r][0])[lane] = v;
        }
        __syncthreads();

        unsigned long long h0[MV_R], h1[MV_R];
        #pragma unroll
        for (int r = 0; r < MV_R; ++r) { h0[r] = 0ull; h1[r] = 0ull; }

        #pragma unroll 4
        for (int kk = 0; kk < D / 2; ++kk) {
            ulonglong2 wv = *(const ulonglong2*)&Wp[kk][2 * lane];
            #pragma unroll
            for (int r = 0; r < MV_R; ++r) {
                unsigned long long xp =
                    *(const unsigned long long*)&xs[rl + r][2 * kk];
                fma2(h0[r], xp, wv.x);
                fma2(h1[r], xp, wv.y);
            }
        }

        const float2 bb = ((const float2*)b)[lane];
        #pragma unroll
        for (int r = 0; r < MV_R; ++r) {
            float2 p0 = *(float2*)&h0[r];
            float2 p1 = *(float2*)&h1[r];
            float hx = p0.x + p0.y + bb.x;
            float hy = p1.x + p1.y + bb.y;
            float nn = hx * hx + hy * hy;
            #pragma unroll
            for (int m = 16; m >= 1; m >>= 1)
                nn += __shfl_xor_sync(0xFFFFFFFFu, nn, m);
            float inv = rsqrtf(fmaxf(nn, EPS2));
            ((float2*)(g_z + (size_t)(rowbase + r) * D))[lane] =
                make_float2(hx * inv, hy * inv);
        }

        // publish: all 64 rows of this block are ready
        __threadfence();
        __syncthreads();
        if (tid == 0)
            asm volatile("st.release.gpu.global.b32 [%0], %1;"
                         :: "l"(&g_flag[blockIdx.x]), "r"(1) : "memory");
    } else {
        // ================= GATHER ROLE: s = sum_p normalize(a_p); out = z.s ===
        const int g    = blockIdx.x - MV_BLOCKS;
        const int row  = g * GA_WPB + warp;
        const int q    = lane & 15;
        const int half = lane >> 4;

        const int u = __ldg(&uidx[row]);
        const float4* base =
            (const float4*)(proto + (size_t)u * (NP * D)) + half * (D / 4) + q;

        // 10 independent LDG.128, all live in registers
        float4 a0 = __ldg(base + 0 * 32);
        float4 a1 = __ldg(base + 1 * 32);
        float4 a2 = __ldg(base + 2 * 32);
        float4 a3 = __ldg(base + 3 * 32);
        float4 a4 = __ldg(base + 4 * 32);
        float4 a5 = __ldg(base + 5 * 32);
        float4 a6 = __ldg(base + 6 * 32);
        float4 a7 = __ldg(base + 7 * 32);
        float4 a8 = __ldg(base + 8 * 32);
        float4 a9 = __ldg(base + 9 * 32);

        float4 s = make_float4(0.f, 0.f, 0.f, 0.f);

        #define PROC(A)                                                       \
        {                                                                     \
            float t = A.x * A.x + A.y * A.y + A.z * A.z + A.w * A.w;          \
            _Pragma("unroll")                                                 \
            for (int m = 8; m >= 1; m >>= 1)                                  \
                t += __shfl_xor_sync(0xFFFFFFFFu, t, m);                      \
            float iv = rsqrtf(fmaxf(t, EPS2));                                \
            s.x = fmaf(A.x, iv, s.x);                                         \
            s.y = fmaf(A.y, iv, s.y);                                         \
            s.z = fmaf(A.z, iv, s.z);                                         \
            s.w = fmaf(A.w, iv, s.w);                                         \
        }

        PROC(a0); PROC(a1); PROC(a2); PROC(a3); PROC(a4);
        PROC(a5); PROC(a6); PROC(a7); PROC(a8); PROC(a9);
        #undef PROC

        // wait for our z (matvec block g>>3); usually already published
        {
            const int* fp = &g_flag[g >> 3];
            int f;
            asm volatile("ld.acquire.gpu.global.b32 %0, [%1];"
                         : "=r"(f) : "l"(fp) : "memory");
            while (!f) {
                __nanosleep(64);
                asm volatile("ld.acquire.gpu.global.b32 %0, [%1];"
                             : "=r"(f) : "l"(fp) : "memory");
            }
        }

        const float4 zq = *((const float4*)(g_z + (size_t)row * D) + q);

        float d = zq.x * s.x + zq.y * s.y + zq.z * s.z + zq.w * s.w;
        #pragma unroll
        for (int m = 16; m >= 1; m >>= 1)
            d += __shfl_xor_sync(0xFFFFFFFFu, d, m);

        if (lane == 0)
            out[row] = d;
    }
}

extern "C" void kernel_launch(void* const* d_in, const int* in_sizes, int n_in,
                              void* d_out, int out_size) {
    const int*   uidx  = (const int*)d_in[0];
    const float* x     = (const float*)d_in[1];
    const float* proto = (const float*)d_in[2];
    const float* W     = (const float*)d_in[3];
    const float* b     = (const float*)d_in[4];
    float* out = (float*)d_out;

    user_memory_overlap<<<NBLOCKS, THREADS>>>(uidx, x, proto, W, b, out);
}

// round 13
// speedup vs baseline: 1.8318x; 1.1548x over previous
#include <cuda_runtime.h>
#include <cuda_bf16.h>
#include <cstdint>

#define NP      20
#define D       64
#define NROWS   16384
#define EPS2    1e-24f              // (1e-12)^2 under rsqrt

#define THREADS    256
#define MV_BLOCKS  256              // matvec: 64 rows/block
#define MV_R       8                // rows per warp in matvec
#define GA_WPB     8                // gather: 1 row/warp
#define GA_BLOCKS  (NROWS / GA_WPB) // 2048
#define NBLOCKS    (MV_BLOCKS + GA_BLOCKS)

__device__ float g_z[NROWS * D];    // normalized queries
__device__ int   g_flag[MV_BLOCKS]; // publish flags (zero-init at module load)

__device__ __forceinline__ void fma2(unsigned long long& acc,
                                     unsigned long long a,
                                     unsigned long long b) {
    asm("fma.rn.f32x2 %0, %1, %2, %0;" : "+l"(acc) : "l"(a), "l"(b));
}

__global__ __launch_bounds__(THREADS, 3)
void user_memory_overlap(const int* __restrict__ uidx,
                         const float* __restrict__ x,
                         const float* __restrict__ proto,
                         const float* __restrict__ W,
                         const float* __restrict__ b,
                         float* __restrict__ out)
{
    __shared__ float2 Wp[D / 2][D];      // 16 KB (matvec blocks only)
    __shared__ float  xs[64][D];         // 16 KB x staging (matvec blocks only)

    const int tid  = threadIdx.x;
    const int warp = tid >> 5;
    const int lane = tid & 31;

    if (blockIdx.x < MV_BLOCKS) {
        // ================= MATVEC ROLE: z = normalize(x@W^T + b) =============
        const int rowbase = blockIdx.x * 64 + warp * MV_R;
        const int rl      = warp * MV_R;

        #pragma unroll
        for (int i = tid; i < D * D / 2; i += THREADS) {
            int d = i >> 5, kk = i & 31;
            Wp[kk][d] = ((const float2*)W)[i];
        }
        #pragma unroll
        for (int r = 0; r < MV_R; ++r) {
            float2 v = ((const float2*)(x + (size_t)(rowbase + r) * D))[lane];
            ((float2*)&xs[rl + r][0])[lane] = v;
        }
        __syncthreads();

        unsigned long long h0[MV_R], h1[MV_R];
        #pragma unroll
        for (int r = 0; r < MV_R; ++r) { h0[r] = 0ull; h1[r] = 0ull; }

        #pragma unroll 4
        for (int kk = 0; kk < D / 2; ++kk) {
            ulonglong2 wv = *(const ulonglong2*)&Wp[kk][2 * lane];
            #pragma unroll
            for (int r = 0; r < MV_R; ++r) {
                unsigned long long xp =
                    *(const unsigned long long*)&xs[rl + r][2 * kk];
                fma2(h0[r], xp, wv.x);
                fma2(h1[r], xp, wv.y);
            }
        }

        const float2 bb = ((const float2*)b)[lane];
        #pragma unroll
        for (int r = 0; r < MV_R; ++r) {
            float2 p0 = *(float2*)&h0[r];
            float2 p1 = *(float2*)&h1[r];
            float hx = p0.x + p0.y + bb.x;
            float hy = p1.x + p1.y + bb.y;
            float nn = hx * hx + hy * hy;
            #pragma unroll
            for (int m = 16; m >= 1; m >>= 1)
                nn += __shfl_xor_sync(0xFFFFFFFFu, nn, m);
            float inv = rsqrtf(fmaxf(nn, EPS2));
            ((float2*)(g_z + (size_t)(rowbase + r) * D))[lane] =
                make_float2(hx * inv, hy * inv);
        }

        // publish: all 64 rows of this block are ready
        __threadfence();
        __syncthreads();
        if (tid == 0)
            asm volatile("st.release.gpu.global.b32 [%0], %1;"
                         :: "l"(&g_flag[blockIdx.x]), "r"(1) : "memory");
    } else {
        // ================= GATHER ROLE: s = sum_p normalize(a_p); out = z.s ===
        const int g    = blockIdx.x - MV_BLOCKS;
        const int row  = g * GA_WPB + warp;
        const int q    = lane & 15;
        const int half = lane >> 4;

        const int u = __ldg(&uidx[row]);
        const float4* base =
            (const float4*)(proto + (size_t)u * (NP * D)) + half * (D / 4) + q;

        // 10 independent LDG.128, all live in registers
        float4 a0 = __ldg(base + 0 * 32);
        float4 a1 = __ldg(base + 1 * 32);
        float4 a2 = __ldg(base + 2 * 32);
        float4 a3 = __ldg(base + 3 * 32);
        float4 a4 = __ldg(base + 4 * 32);
        float4 a5 = __ldg(base + 5 * 32);
        float4 a6 = __ldg(base + 6 * 32);
        float4 a7 = __ldg(base + 7 * 32);
        float4 a8 = __ldg(base + 8 * 32);
        float4 a9 = __ldg(base + 9 * 32);

        float4 s = make_float4(0.f, 0.f, 0.f, 0.f);

        #define PROC(A)                                                       \
        {                                                                     \
            float t = A.x * A.x + A.y * A.y + A.z * A.z + A.w * A.w;          \
            _Pragma("unroll")                                                 \
            for (int m = 8; m >= 1; m >>= 1)                                  \
                t += __shfl_xor_sync(0xFFFFFFFFu, t, m);                      \
            float iv = rsqrtf(fmaxf(t, EPS2));                                \
            s.x = fmaf(A.x, iv, s.x);                                         \
            s.y = fmaf(A.y, iv, s.y);                                         \
            s.z = fmaf(A.z, iv, s.z);                                         \
            s.w = fmaf(A.w, iv, s.w);                                         \
        }

        PROC(a0); PROC(a1); PROC(a2); PROC(a3); PROC(a4);
        PROC(a5); PROC(a6); PROC(a7); PROC(a8); PROC(a9);
        #undef PROC

        // wait for our z (matvec block g>>3); usually already published
        {
            const int* fp = &g_flag[g >> 3];
            int f;
            asm volatile("ld.acquire.gpu.global.b32 %0, [%1];"
                         : "=r"(f) : "l"(fp) : "memory");
            while (!f) {
                __nanosleep(64);
                asm volatile("ld.acquire.gpu.global.b32 %0, [%1];"
                             : "=r"(f) : "l"(fp) : "memory");
            }
        }

        const float4 zq = *((const float4*)(g_z + (size_t)row * D) + q);

        float d = zq.x * s.x + zq.y * s.y + zq.z * s.z + zq.w * s.w;
        #pragma unroll
        for (int m = 16; m >= 1; m >>= 1)
            d += __shfl_xor_sync(0xFFFFFFFFu, d, m);

        if (lane == 0)
            out[row] = d;
    }
}

extern "C" void kernel_launch(void* const* d_in, const int* in_sizes, int n_in,
                              void* d_out, int out_size) {
    const int*   uidx  = (const int*)d_in[0];
    const float* x     = (const float*)d_in[1];
    const float* proto = (const float*)d_in[2];
    const float* W     = (const float*)d_in[3];
    const float* b     = (const float*)d_in[4];
    float* out = (float*)d_out;

    user_memory_overlap<<<NBLOCKS, THREADS>>>(uidx, x, proto, W, b, out);
}

// round 16
// speedup vs baseline: 1.8539x; 1.0120x over previous
#include <cuda_runtime.h>
#include <cuda_bf16.h>
#include <cstdint>

#define NP      20
#define D       64
#define NROWS   16384
#define EPS2    1e-24f              // (1e-12)^2 under rsqrt

#define THREADS    256
#define MV_BLOCKS  256              // matvec: 64 rows/block
#define MV_R       8                // rows per warp in matvec
#define GA_WPB     8                // gather: 1 row/warp
#define GA_BLOCKS  (NROWS / GA_WPB) // 2048
#define NBLOCKS    (MV_BLOCKS + GA_BLOCKS)

__device__ float g_z[NROWS * D];    // normalized queries
__device__ int   g_flag[MV_BLOCKS]; // publish flags (zero-init at module load)

__device__ __forceinline__ void fma2(unsigned long long& acc,
                                     unsigned long long a,
                                     unsigned long long b) {
    asm("fma.rn.f32x2 %0, %1, %2, %0;" : "+l"(acc) : "l"(a), "l"(b));
}

__global__ __launch_bounds__(THREADS, 4)
void user_memory_overlap(const int* __restrict__ uidx,
                         const float* __restrict__ x,
                         const float* __restrict__ proto,
                         const float* __restrict__ W,
                         const float* __restrict__ b,
                         float* __restrict__ out)
{
    __shared__ float2 Wp[D / 2][D];      // 16 KB (matvec blocks only)
    __shared__ float  xs[64][D];         // 16 KB x staging (matvec blocks only)

    const int tid  = threadIdx.x;
    const int warp = tid >> 5;
    const int lane = tid & 31;

    if (blockIdx.x < MV_BLOCKS) {
        // ================= MATVEC ROLE: z = normalize(x@W^T + b) =============
        const int rowbase = blockIdx.x * 64 + warp * MV_R;
        const int rl      = warp * MV_R;

        #pragma unroll
        for (int i = tid; i < D * D / 2; i += THREADS) {
            int d = i >> 5, kk = i & 31;
            Wp[kk][d] = ((const float2*)W)[i];
        }
        #pragma unroll
        for (int r = 0; r < MV_R; ++r) {
            float2 v = ((const float2*)(x + (size_t)(rowbase + r) * D))[lane];
            ((float2*)&xs[rl + r][0])[lane] = v;
        }
        __syncthreads();

        unsigned long long h0[MV_R], h1[MV_R];
        #pragma unroll
        for (int r = 0; r < MV_R; ++r) { h0[r] = 0ull; h1[r] = 0ull; }

        #pragma unroll 4
        for (int kk = 0; kk < D / 2; ++kk) {
            ulonglong2 wv = *(const ulonglong2*)&Wp[kk][2 * lane];
            #pragma unroll
            for (int r = 0; r < MV_R; ++r) {
                unsigned long long xp =
                    *(const unsigned long long*)&xs[rl + r][2 * kk];
                fma2(h0[r], xp, wv.x);
                fma2(h1[r], xp, wv.y);
            }
        }

        const float2 bb = ((const float2*)b)[lane];
        #pragma unroll
        for (int r = 0; r < MV_R; ++r) {
            float2 p0 = *(float2*)&h0[r];
            float2 p1 = *(float2*)&h1[r];
            float hx = p0.x + p0.y + bb.x;
            float hy = p1.x + p1.y + bb.y;
            float nn = hx * hx + hy * hy;
            #pragma unroll
            for (int m = 16; m >= 1; m >>= 1)
                nn += __shfl_xor_sync(0xFFFFFFFFu, nn, m);
            float inv = rsqrtf(fmaxf(nn, EPS2));
            ((float2*)(g_z + (size_t)(rowbase + r) * D))[lane] =
                make_float2(hx * inv, hy * inv);
        }

        // publish: all 64 rows of this block are ready
        __threadfence();
        __syncthreads();
        if (tid == 0)
            asm volatile("st.release.gpu.global.b32 [%0], %1;"
                         :: "l"(&g_flag[blockIdx.x]), "r"(1) : "memory");
    } else {
        // ================= GATHER ROLE: s = sum_p normalize(a_p); out = z.s ===
        const int g    = blockIdx.x - MV_BLOCKS;
        const int row  = g * GA_WPB + warp;
        const int q    = lane & 15;
        const int half = lane >> 4;

        const int u = __ldg(&uidx[row]);
        const float4* base =
            (const float4*)(proto + (size_t)u * (NP * D)) + half * (D / 4) + q;

        // 10 independent LDG.128, all live in registers
        float4 a0 = __ldg(base + 0 * 32);
        float4 a1 = __ldg(base + 1 * 32);
        float4 a2 = __ldg(base + 2 * 32);
        float4 a3 = __ldg(base + 3 * 32);
        float4 a4 = __ldg(base + 4 * 32);
        float4 a5 = __ldg(base + 5 * 32);
        float4 a6 = __ldg(base + 6 * 32);
        float4 a7 = __ldg(base + 7 * 32);
        float4 a8 = __ldg(base + 8 * 32);
        float4 a9 = __ldg(base + 9 * 32);

        float4 s = make_float4(0.f, 0.f, 0.f, 0.f);

        #define PROC(A)                                                       \
        {                                                                     \
            float t = A.x * A.x + A.y * A.y + A.z * A.z + A.w * A.w;          \
            _Pragma("unroll")                                                 \
            for (int m = 8; m >= 1; m >>= 1)                                  \
                t += __shfl_xor_sync(0xFFFFFFFFu, t, m);                      \
            float iv = rsqrtf(fmaxf(t, EPS2));                                \
            s.x = fmaf(A.x, iv, s.x);                                         \
            s.y = fmaf(A.y, iv, s.y);                                         \
            s.z = fmaf(A.z, iv, s.z);                                         \
            s.w = fmaf(A.w, iv, s.w);                                         \
        }

        PROC(a0); PROC(a1); PROC(a2); PROC(a3); PROC(a4);
        PROC(a5); PROC(a6); PROC(a7); PROC(a8); PROC(a9);
        #undef PROC

        // wait for our z (matvec block g>>3); usually already published
        {
            const int* fp = &g_flag[g >> 3];
            int f;
            asm volatile("ld.acquire.gpu.global.b32 %0, [%1];"
                         : "=r"(f) : "l"(fp) : "memory");
            while (!f) {
                __nanosleep(64);
                asm volatile("ld.acquire.gpu.global.b32 %0, [%1];"
                             : "=r"(f) : "l"(fp) : "memory");
            }
        }

        // z read happens after anchor registers are dead -> low peak pressure
        const float4 zq = *((const float4*)(g_z + (size_t)row * D) + q);

        float d = zq.x * s.x + zq.y * s.y + zq.z * s.z + zq.w * s.w;
        #pragma unroll
        for (int m = 16; m >= 1; m >>= 1)
            d += __shfl_xor_sync(0xFFFFFFFFu, d, m);

        if (lane == 0)
            out[row] = d;
    }
}

extern "C" void kernel_launch(void* const* d_in, const int* in_sizes, int n_in,
                              void* d_out, int out_size) {
    const int*   uidx  = (const int*)d_in[0];
    const float* x     = (const float*)d_in[1];
    const float* proto = (const float*)d_in[2];
    const float* W     = (const float*)d_in[3];
    const float* b     = (const float*)d_in[4];
    float* out = (float*)d_out;

    user_memory_overlap<<<NBLOCKS, THREADS>>>(uidx, x, proto, W, b, out);
}